// round 8
// baseline (speedup 1.0000x reference)
#include <cuda_runtime.h>
#include <cstdint>

#define HH 512
#define WW 512
#define MAXB 16
#define MAXBN 512          // max B*N slabs
#define NCH 4              // H-chunks per slab
#define CHROWS (HH / NCH)  // 128 rows per chunk

// Scratch (device globals — zero-initialized at module load; no allocation).
__device__ int    g_xmin [MAXB * HH];
__device__ int    g_xmax [MAXB * HH];
__device__ float4 g_theta[MAXB];                 // {sl_l, ic_l, sl_r, ic_r}
__device__ float  g_colp [MAXBN][NCH][WW];       // per-chunk column sums
__device__ float  g_part [MAXBN][NCH][2];        // per-chunk {inst, vert}
__device__ int    g_cnt  [MAXBN];                // size-chunk combine election

// ---------------------------------------------------------------------------
// Kernel A: per-row min/max positive column of seg channel 1. Pure stream.
// Grid = B*64 blocks x 256 thr (8 warps); warp owns one row (float4, MLP=8).
// Small blocks -> faster ramp/tail for this short kernel.
// ---------------------------------------------------------------------------
__global__ void __launch_bounds__(256) minmax_kernel(const float* __restrict__ seg)
{
    const int b    = blockIdx.x >> 6;
    const int blk  = blockIdx.x & 63;
    const int lane = threadIdx.x & 31;
    const int warp = threadIdx.x >> 5;

    const int h = blk * 8 + warp;
    const float4* row = (const float4*)(seg + (size_t)b * HH * WW * 2
                                            + (size_t)h * WW * 2);
    int mn = WW, mx = -1;
    #pragma unroll
    for (int i = 0; i < 8; i++) {
        const int j = lane + i * 32;        // float4 idx; pixels 2j (x,y), 2j+1 (z,w)
        const float4 v = __ldcg(&row[j]);
        if (v.y > 0.0f) { mn = min(mn, 2 * j);     mx = max(mx, 2 * j); }
        if (v.w > 0.0f) { mn = min(mn, 2 * j + 1); mx = max(mx, 2 * j + 1); }
    }
    #pragma unroll
    for (int o = 16; o; o >>= 1) {
        mn = min(mn, __shfl_down_sync(0xffffffffu, mn, o));
        mx = max(mx, __shfl_down_sync(0xffffffffu, mx, o));
    }
    if (lane == 0) {
        g_xmin[b * HH + h] = mn;
        g_xmax[b * HH + h] = mx;
    }
}

// ---------------------------------------------------------------------------
// Kernel B: trimmed weighted-LS fit -> theta per image. Grid = B, tiny.
// ---------------------------------------------------------------------------
__global__ void __launch_bounds__(512) fit_kernel()
{
    const int b    = blockIdx.x;
    const int tid  = threadIdx.x;
    const int lane = tid & 31;
    const int warp = tid >> 5;

    const int xmin_i = g_xmin[b * HH + tid];
    const int xmax_i = g_xmax[b * HH + tid];
    const int valid  = (xmax_i >= 0 && xmin_i != xmax_i) ? 1 : 0;

    __shared__ int   wtot[16];
    __shared__ float acc[7];
    unsigned bal = __ballot_sync(0xffffffffu, valid);
    int pre = __popc(bal & ((1u << lane) - 1u));
    if (lane == 0) wtot[warp] = __popc(bal);
    if (tid < 7) acc[tid] = 0.0f;
    __syncthreads();

    int off = 0, nvalid = 0;
    #pragma unroll
    for (int i = 0; i < 16; i++) {
        int t = wtot[i];
        nvalid += t;
        if (i < warp) off += t;
    }
    const int rank = off + pre;

    int drop = (int)((float)nvalid * 0.15f);   // trunc, matches astype(int32)
    if (drop < 1) drop = 1;
    const int keep = valid && (rank >= drop) && (rank < nvalid - drop);

    const float w  = keep ? 1.0f : 0.0f;
    const float y  = (float)tid;
    const float xl = (float)xmin_i;
    const float xr = (float)xmax_i;

    float v0 = w;
    float v1 = w * y;
    float v2 = w * y * y;
    float v3 = w * xl;
    float v4 = w * y * xl;
    float v5 = w * xr;
    float v6 = w * y * xr;

    #pragma unroll
    for (int o = 16; o; o >>= 1) {
        v0 += __shfl_down_sync(0xffffffffu, v0, o);
        v1 += __shfl_down_sync(0xffffffffu, v1, o);
        v2 += __shfl_down_sync(0xffffffffu, v2, o);
        v3 += __shfl_down_sync(0xffffffffu, v3, o);
        v4 += __shfl_down_sync(0xffffffffu, v4, o);
        v5 += __shfl_down_sync(0xffffffffu, v5, o);
        v6 += __shfl_down_sync(0xffffffffu, v6, o);
    }
    if (lane == 0) {
        atomicAdd(&acc[0], v0);
        atomicAdd(&acc[1], v1);
        atomicAdd(&acc[2], v2);
        atomicAdd(&acc[3], v3);
        atomicAdd(&acc[4], v4);
        atomicAdd(&acc[5], v5);
        atomicAdd(&acc[6], v6);
    }
    __syncthreads();

    if (tid == 0) {
        const float Sw  = acc[0], Sy  = acc[1], Syy = acc[2];
        const float Sxl = acc[3], Sxyl = acc[4];
        const float Sxr = acc[5], Sxyr = acc[6];

        const float det  = Syy * Sw - Sy * Sy;
        const float safe = (det > 0.0f) ? det : 1.0f;

        float sl_l = (Sw * Sxyl - Sy * Sxl) / safe;
        float ic_l = (-Sy * Sxyl + Syy * Sxl) / safe;
        float sl_r = (Sw * Sxyr - Sy * Sxr) / safe;
        float ic_r = (-Sy * Sxyr + Syy * Sxr) / safe;
        if (!(det > 0.0f)) { sl_l = ic_l = sl_r = ic_r = 0.0f; }

        g_theta[b] = make_float4(sl_l, ic_l, sl_r, ic_r);
    }
}

// ---------------------------------------------------------------------------
// Kernel C: one block per (bn, chunk); chunk = 128 rows. Reduction-free theta
// prologue, then streaming with EXPLICIT 4-deep load batches (forces MLP=4
// per thread; ~64KB in flight per SM at 2 resident blocks > BW-delay need).
// 512 thr = 4 row-groups x 128 col-threads; thread (g, c) owns columns
// 4c..4c+3, local rows g, g+4, ..., g+124.
// ---------------------------------------------------------------------------
__global__ void __launch_bounds__(512) size_kernel(const float* __restrict__ pad,
                                                   float* __restrict__ out,
                                                   int N)
{
    const int bn   = blockIdx.x >> 2;
    const int ch   = blockIdx.x & 3;
    const int b    = bn / N;
    const int tid  = threadIdx.x;
    const int lane = tid & 31;
    const int warp = tid >> 5;
    const int g    = tid >> 7;        // row group 0..3
    const int c    = tid & 127;       // column group: columns 4c..4c+3
    const int h0   = ch * CHROWS;     // first global row of this chunk

    __shared__ float    su [CHROWS];
    __shared__ float    su2[CHROWS];
    __shared__ float    scol[WW];
    __shared__ unsigned grpmask[4];
    __shared__ float    sred[16];

    // reconstruct unit for this chunk's rows (no reduction, no extra sync)
    if (tid < CHROWS) {
        const float4 th = g_theta[b];           // {sl_l, ic_l, sl_r, ic_r}
        const float y = (float)(h0 + tid);
        float width = (y * th.z + th.w) - (y * th.x + th.y);
        width = fmaxf(width, 1.0f);
        const float u = 3.25f / width;
        su [tid] = u;
        su2[tid] = u * u;
    }
    scol[tid] = 0.0f;
    if (tid < 4) grpmask[tid] = 0u;
    __syncthreads();

    const float4* p = (const float4*)(pad + (size_t)bn * HH * WW
                                          + (size_t)h0 * WW) + c;

    float4 colacc = make_float4(0.f, 0.f, 0.f, 0.f);
    float  inst   = 0.0f;
    unsigned lm   = 0u;

    #pragma unroll
    for (int kk = 0; kk < 32; kk += 4) {
        float4 vv[4];
        #pragma unroll
        for (int i = 0; i < 4; i++)
            vv[i] = __ldcg(&p[(size_t)(g + 4 * (kk + i)) * (WW / 4)]);
        #pragma unroll
        for (int i = 0; i < 4; i++) {
            const int k = kk + i;
            const int h = g + 4 * k;      // local row
            const float4 v = vv[i];
            const float u1 = su[h], u2 = su2[h];
            colacc.x = fmaf(u1, v.x, colacc.x);
            colacc.y = fmaf(u1, v.y, colacc.y);
            colacc.z = fmaf(u1, v.z, colacc.z);
            colacc.w = fmaf(u1, v.w, colacc.w);
            inst = fmaf(u2, (v.x + v.y) + (v.z + v.w), inst);
            if (fmaxf(fmaxf(v.x, v.y), fmaxf(v.z, v.w)) > 0.5f)
                lm |= (1u << k);
        }
    }

    // row-occupied bits: OR across the 4 warps of each group
    {
        unsigned m = __reduce_or_sync(0xffffffffu, lm);
        if (lane == 0 && m) atomicOr(&grpmask[g], m);
    }

    // per-column sums: combine 4 row-groups via shared atomics
    atomicAdd(&scol[4 * c + 0], colacc.x);
    atomicAdd(&scol[4 * c + 1], colacc.y);
    atomicAdd(&scol[4 * c + 2], colacc.z);
    atomicAdd(&scol[4 * c + 3], colacc.w);

    // instance partial (block sum)
    float s = inst;
    #pragma unroll
    for (int o = 16; o; o >>= 1) s += __shfl_down_sync(0xffffffffu, s, o);
    if (lane == 0) sred[warp] = s;
    __syncthreads();

    // vertical partial: local row r handled by group r&3, iteration r>>2
    float vv2 = 0.0f;
    if (tid < CHROWS) {
        const unsigned bit = (grpmask[tid & 3] >> (tid >> 2)) & 1u;
        vv2 = bit ? su[tid] : 0.0f;
    }
    #pragma unroll
    for (int o = 16; o; o >>= 1) vv2 += __shfl_down_sync(0xffffffffu, vv2, o);

    __shared__ float svert[4];
    if (lane == 0 && warp < 4) svert[warp] = vv2;
    __syncthreads();

    if (tid == 0) {
        float ti = 0.0f;
        #pragma unroll
        for (int i = 0; i < 16; i++) ti += sred[i];
        float tv = (svert[0] + svert[1]) + (svert[2] + svert[3]);
        g_part[bn][ch][0] = ti;
        g_part[bn][ch][1] = tv;
    }

    // column partials to scratch (coalesced)
    g_colp[bn][ch][tid] = scol[tid];
    __threadfence();

    // elect last chunk-block of this slab to combine
    __shared__ int isLastC;
    __syncthreads();
    if (tid == 0) isLastC = (atomicAdd(&g_cnt[bn], 1) == NCH - 1);
    __syncthreads();
    if (!isLastC) return;
    __threadfence();

    // horizontal: per-column sum over chunks (fixed order), then block max
    float colsum = __ldcg(&g_colp[bn][0][tid]);
    colsum += __ldcg(&g_colp[bn][1][tid]);
    colsum += __ldcg(&g_colp[bn][2][tid]);
    colsum += __ldcg(&g_colp[bn][3][tid]);

    float m = colsum;
    #pragma unroll
    for (int o = 16; o; o >>= 1) m = fmaxf(m, __shfl_down_sync(0xffffffffu, m, o));
    if (lane == 0) sred[warp] = m;
    __syncthreads();

    if (tid == 0) {
        float hmax = sred[0];
        #pragma unroll
        for (int i = 1; i < 16; i++) hmax = fmaxf(hmax, sred[i]);

        float ti = 0.0f, tv = 0.0f;
        #pragma unroll
        for (int i = 0; i < NCH; i++) {
            ti += __ldcg(&g_part[bn][i][0]);
            tv += __ldcg(&g_part[bn][i][1]);
        }
        out[bn * 3 + 0] = ti;
        out[bn * 3 + 1] = hmax;
        out[bn * 3 + 2] = tv;

        g_cnt[bn] = 0;               // reset for the next graph replay
    }
}

// ---------------------------------------------------------------------------
extern "C" void kernel_launch(void* const* d_in, const int* in_sizes, int n_in,
                              void* d_out, int out_size)
{
    const float* seg = (const float*)d_in[0];   // [B, H, W, 2]
    const float* pad = (const float*)d_in[1];   // [B, N, H, W]
    float* out = (float*)d_out;                 // [B, N, 3]

    const int B = in_sizes[0] / (HH * WW * 2);
    const int N = in_sizes[1] / (B * HH * WW);

    minmax_kernel<<<B * 64, 256>>>(seg);
    fit_kernel<<<B, 512>>>();
    size_kernel<<<B * N * NCH, 512>>>(pad, out, N);
}

// round 9
// speedup vs baseline: 1.1415x; 1.1415x over previous
#include <cuda_runtime.h>
#include <cstdint>

#define HH 512
#define WW 512
#define MAXB 16
#define MAXBN 512          // max B*N slabs
#define NCH 4              // H-chunks per slab
#define CHROWS (HH / NCH)  // 128 rows per chunk

// Scratch (device globals — zero-initialized at module load; no allocation).
__device__ int    g_xmin [MAXB * HH];
__device__ int    g_xmax [MAXB * HH];
__device__ float4 g_theta[MAXB];                 // {sl_l, ic_l, sl_r, ic_r}
__device__ int    g_count[MAXB];                 // minmax->fit election
__device__ float  g_colp [MAXBN][NCH][WW];       // per-chunk column sums
__device__ float  g_part [MAXBN][NCH][2];        // per-chunk {inst, vert}
__device__ int    g_cnt  [MAXBN];                // size-chunk combine election

// ---------------------------------------------------------------------------
// Kernel A: per-row min/max positive column of seg channel 1 (explicit 8-deep
// load batch per lane -> true MLP=8), fused with the trimmed WLS fit done by
// the elected last block per image. Grid = B*32, 512 thr, warp owns one row.
// ---------------------------------------------------------------------------
__global__ void __launch_bounds__(512) minmax_fit_kernel(const float* __restrict__ seg)
{
    const int b    = blockIdx.x >> 5;
    const int blk  = blockIdx.x & 31;
    const int tid  = threadIdx.x;
    const int lane = tid & 31;
    const int warp = tid >> 5;

    const int h = blk * 16 + warp;
    const float4* row = (const float4*)(seg + (size_t)b * HH * WW * 2
                                            + (size_t)h * WW * 2);

    // issue all 8 loads before any consume (separate vars defeat collapsing)
    const float4 v0 = row[lane +   0];
    const float4 v1 = row[lane +  32];
    const float4 v2 = row[lane +  64];
    const float4 v3 = row[lane +  96];
    const float4 v4 = row[lane + 128];
    const float4 v5 = row[lane + 160];
    const float4 v6 = row[lane + 192];
    const float4 v7 = row[lane + 224];

    int mn = WW, mx = -1;
    #define MM_ACC(v, base)                                                    \
        do {                                                                   \
            const int p0 = 2 * (lane + (base));                                \
            if ((v).y > 0.0f) { mn = min(mn, p0);     mx = max(mx, p0); }      \
            if ((v).w > 0.0f) { mn = min(mn, p0 + 1); mx = max(mx, p0 + 1); }  \
        } while (0)
    MM_ACC(v0,   0); MM_ACC(v1,  32); MM_ACC(v2,  64); MM_ACC(v3,  96);
    MM_ACC(v4, 128); MM_ACC(v5, 160); MM_ACC(v6, 192); MM_ACC(v7, 224);
    #undef MM_ACC

    #pragma unroll
    for (int o = 16; o; o >>= 1) {
        mn = min(mn, __shfl_down_sync(0xffffffffu, mn, o));
        mx = max(mx, __shfl_down_sync(0xffffffffu, mx, o));
    }
    if (lane == 0) {
        g_xmin[b * HH + h] = mn;
        g_xmax[b * HH + h] = mx;
    }
    __threadfence();

    // ---- elect the last block of this image to run the fit ----
    __shared__ int isLast;
    __syncthreads();
    if (tid == 0) isLast = (atomicAdd(&g_count[b], 1) == 31);
    __syncthreads();
    if (!isLast) return;
    __threadfence();

    const int xmin_i = __ldcg(&g_xmin[b * HH + tid]);
    const int xmax_i = __ldcg(&g_xmax[b * HH + tid]);
    const int valid  = (xmax_i >= 0 && xmin_i != xmax_i) ? 1 : 0;

    __shared__ int   wtot[16];
    __shared__ float acc[7];
    unsigned bal = __ballot_sync(0xffffffffu, valid);
    int pre = __popc(bal & ((1u << lane) - 1u));
    if (lane == 0) wtot[warp] = __popc(bal);
    if (tid < 7) acc[tid] = 0.0f;
    __syncthreads();

    int off = 0, nvalid = 0;
    #pragma unroll
    for (int i = 0; i < 16; i++) {
        int t = wtot[i];
        nvalid += t;
        if (i < warp) off += t;
    }
    const int rank = off + pre;

    int drop = (int)((float)nvalid * 0.15f);   // trunc, matches astype(int32)
    if (drop < 1) drop = 1;
    const int keep = valid && (rank >= drop) && (rank < nvalid - drop);

    const float w  = keep ? 1.0f : 0.0f;
    const float y  = (float)tid;
    const float xl = (float)xmin_i;
    const float xr = (float)xmax_i;

    float s0 = w;
    float s1 = w * y;
    float s2 = w * y * y;
    float s3 = w * xl;
    float s4 = w * y * xl;
    float s5 = w * xr;
    float s6 = w * y * xr;

    #pragma unroll
    for (int o = 16; o; o >>= 1) {
        s0 += __shfl_down_sync(0xffffffffu, s0, o);
        s1 += __shfl_down_sync(0xffffffffu, s1, o);
        s2 += __shfl_down_sync(0xffffffffu, s2, o);
        s3 += __shfl_down_sync(0xffffffffu, s3, o);
        s4 += __shfl_down_sync(0xffffffffu, s4, o);
        s5 += __shfl_down_sync(0xffffffffu, s5, o);
        s6 += __shfl_down_sync(0xffffffffu, s6, o);
    }
    if (lane == 0) {
        atomicAdd(&acc[0], s0);
        atomicAdd(&acc[1], s1);
        atomicAdd(&acc[2], s2);
        atomicAdd(&acc[3], s3);
        atomicAdd(&acc[4], s4);
        atomicAdd(&acc[5], s5);
        atomicAdd(&acc[6], s6);
    }
    __syncthreads();

    if (tid == 0) {
        const float Sw  = acc[0], Sy  = acc[1], Syy = acc[2];
        const float Sxl = acc[3], Sxyl = acc[4];
        const float Sxr = acc[5], Sxyr = acc[6];

        const float det  = Syy * Sw - Sy * Sy;
        const float safe = (det > 0.0f) ? det : 1.0f;

        float sl_l = (Sw * Sxyl - Sy * Sxl) / safe;
        float ic_l = (-Sy * Sxyl + Syy * Sxl) / safe;
        float sl_r = (Sw * Sxyr - Sy * Sxr) / safe;
        float ic_r = (-Sy * Sxyr + Syy * Sxr) / safe;
        if (!(det > 0.0f)) { sl_l = ic_l = sl_r = ic_r = 0.0f; }

        g_theta[b]  = make_float4(sl_l, ic_l, sl_r, ic_r);
        g_count[b]  = 0;              // reset for the next graph replay
    }
}

// ---------------------------------------------------------------------------
// Kernel C: one block per (bn, chunk); chunk = 128 rows. Reduction-free theta
// prologue; plain float4 loads (best measured config). 512 thr = 4 row-groups
// x 128 col-threads; thread (g, c) owns columns 4c..4c+3, rows g+4k.
// ---------------------------------------------------------------------------
__global__ void __launch_bounds__(512) size_kernel(const float* __restrict__ pad,
                                                   float* __restrict__ out,
                                                   int N)
{
    const int bn   = blockIdx.x >> 2;
    const int ch   = blockIdx.x & 3;
    const int b    = bn / N;
    const int tid  = threadIdx.x;
    const int lane = tid & 31;
    const int warp = tid >> 5;
    const int g    = tid >> 7;        // row group 0..3
    const int c    = tid & 127;       // column group: columns 4c..4c+3
    const int h0   = ch * CHROWS;     // first global row of this chunk

    __shared__ float    su [CHROWS];
    __shared__ float    su2[CHROWS];
    __shared__ float    scol[WW];
    __shared__ unsigned grpmask[4];
    __shared__ float    sred[16];

    // reconstruct unit for this chunk's rows (no reduction, no extra sync)
    if (tid < CHROWS) {
        const float4 th = g_theta[b];           // {sl_l, ic_l, sl_r, ic_r}
        const float y = (float)(h0 + tid);
        float width = (y * th.z + th.w) - (y * th.x + th.y);
        width = fmaxf(width, 1.0f);
        const float u = 3.25f / width;
        su [tid] = u;
        su2[tid] = u * u;
    }
    scol[tid] = 0.0f;
    if (tid < 4) grpmask[tid] = 0u;
    __syncthreads();

    const float4* p = (const float4*)(pad + (size_t)bn * HH * WW
                                          + (size_t)h0 * WW) + c;

    float4 colacc = make_float4(0.f, 0.f, 0.f, 0.f);
    float  inst   = 0.0f;
    unsigned lm   = 0u;

    #pragma unroll 8
    for (int k = 0; k < 32; k++) {
        const int h = g + 4 * k;      // local row
        const float4 v = p[(size_t)h * (WW / 4)];
        const float u1 = su[h], u2 = su2[h];
        colacc.x = fmaf(u1, v.x, colacc.x);
        colacc.y = fmaf(u1, v.y, colacc.y);
        colacc.z = fmaf(u1, v.z, colacc.z);
        colacc.w = fmaf(u1, v.w, colacc.w);
        inst = fmaf(u2, (v.x + v.y) + (v.z + v.w), inst);
        if (v.x > 0.5f || v.y > 0.5f || v.z > 0.5f || v.w > 0.5f)
            lm |= (1u << k);
    }

    // row-occupied bits: OR across the 4 warps of each group
    {
        unsigned m = __reduce_or_sync(0xffffffffu, lm);
        if (lane == 0 && m) atomicOr(&grpmask[g], m);
    }

    // per-column sums: combine 4 row-groups via shared atomics
    atomicAdd(&scol[4 * c + 0], colacc.x);
    atomicAdd(&scol[4 * c + 1], colacc.y);
    atomicAdd(&scol[4 * c + 2], colacc.z);
    atomicAdd(&scol[4 * c + 3], colacc.w);

    // instance partial (block sum)
    float s = inst;
    #pragma unroll
    for (int o = 16; o; o >>= 1) s += __shfl_down_sync(0xffffffffu, s, o);
    if (lane == 0) sred[warp] = s;
    __syncthreads();

    // vertical partial: local row r handled by group r&3, iteration r>>2
    float vv = 0.0f;
    if (tid < CHROWS) {
        const unsigned bit = (grpmask[tid & 3] >> (tid >> 2)) & 1u;
        vv = bit ? su[tid] : 0.0f;
    }
    #pragma unroll
    for (int o = 16; o; o >>= 1) vv += __shfl_down_sync(0xffffffffu, vv, o);

    __shared__ float svert[4];
    if (lane == 0 && warp < 4) svert[warp] = vv;
    __syncthreads();

    if (tid == 0) {
        float ti = 0.0f;
        #pragma unroll
        for (int i = 0; i < 16; i++) ti += sred[i];
        float tv = (svert[0] + svert[1]) + (svert[2] + svert[3]);
        g_part[bn][ch][0] = ti;
        g_part[bn][ch][1] = tv;
    }

    // column partials to scratch (coalesced)
    g_colp[bn][ch][tid] = scol[tid];
    __threadfence();

    // elect last chunk-block of this slab to combine
    __shared__ int isLastC;
    __syncthreads();
    if (tid == 0) isLastC = (atomicAdd(&g_cnt[bn], 1) == NCH - 1);
    __syncthreads();
    if (!isLastC) return;
    __threadfence();

    // horizontal: per-column sum over chunks (fixed order), then block max
    float colsum = __ldcg(&g_colp[bn][0][tid]);
    colsum += __ldcg(&g_colp[bn][1][tid]);
    colsum += __ldcg(&g_colp[bn][2][tid]);
    colsum += __ldcg(&g_colp[bn][3][tid]);

    float m = colsum;
    #pragma unroll
    for (int o = 16; o; o >>= 1) m = fmaxf(m, __shfl_down_sync(0xffffffffu, m, o));
    if (lane == 0) sred[warp] = m;
    __syncthreads();

    if (tid == 0) {
        float hmax = sred[0];
        #pragma unroll
        for (int i = 1; i < 16; i++) hmax = fmaxf(hmax, sred[i]);

        float ti = 0.0f, tv = 0.0f;
        #pragma unroll
        for (int i = 0; i < NCH; i++) {
            ti += __ldcg(&g_part[bn][i][0]);
            tv += __ldcg(&g_part[bn][i][1]);
        }
        out[bn * 3 + 0] = ti;
        out[bn * 3 + 1] = hmax;
        out[bn * 3 + 2] = tv;

        g_cnt[bn] = 0;               // reset for the next graph replay
    }
}

// ---------------------------------------------------------------------------
extern "C" void kernel_launch(void* const* d_in, const int* in_sizes, int n_in,
                              void* d_out, int out_size)
{
    const float* seg = (const float*)d_in[0];   // [B, H, W, 2]
    const float* pad = (const float*)d_in[1];   // [B, N, H, W]
    float* out = (float*)d_out;                 // [B, N, 3]

    const int B = in_sizes[0] / (HH * WW * 2);
    const int N = in_sizes[1] / (B * HH * WW);

    minmax_fit_kernel<<<B * 32, 512>>>(seg);
    size_kernel<<<B * N * NCH, 512>>>(pad, out, N);
}

// round 10
// speedup vs baseline: 1.1472x; 1.0050x over previous
#include <cuda_runtime.h>
#include <cstdint>

#define HH 512
#define WW 512
#define MAXB 16
#define MAXBN 512          // max B*N slabs
#define NCH 4              // H-chunks per slab
#define CHROWS (HH / NCH)  // 128 rows per chunk

// Scratch (device globals — zero-initialized at module load; no allocation).
__device__ int    g_xmin [MAXB * HH];
__device__ int    g_xmax [MAXB * HH];
__device__ float4 g_theta[MAXB];                 // {sl_l, ic_l, sl_r, ic_r}
__device__ int    g_ready[MAXB];                 // theta published flag
__device__ int    g_done [MAXB];                 // size-block completions/image
__device__ float  g_colp [MAXBN][NCH][WW];       // per-chunk column sums
__device__ float  g_part [MAXBN][NCH][2];        // per-chunk {inst, vert}
__device__ int    g_cnt  [MAXBN];                // size-chunk combine election

// ---------------------------------------------------------------------------
// Kernel A: pure per-row min/max positive column of seg channel 1.
// Explicit 8-deep load batch per lane (true MLP=8). Grid = B*32, 512 thr,
// warp owns one row. No fences/elections — kernel boundary orders writes.
// ---------------------------------------------------------------------------
__global__ void __launch_bounds__(512) minmax_kernel(const float* __restrict__ seg)
{
    const int b    = blockIdx.x >> 5;
    const int blk  = blockIdx.x & 31;
    const int lane = threadIdx.x & 31;
    const int warp = threadIdx.x >> 5;

    const int h = blk * 16 + warp;
    const float4* row = (const float4*)(seg + (size_t)b * HH * WW * 2
                                            + (size_t)h * WW * 2);

    const float4 v0 = row[lane +   0];
    const float4 v1 = row[lane +  32];
    const float4 v2 = row[lane +  64];
    const float4 v3 = row[lane +  96];
    const float4 v4 = row[lane + 128];
    const float4 v5 = row[lane + 160];
    const float4 v6 = row[lane + 192];
    const float4 v7 = row[lane + 224];

    int mn = WW, mx = -1;
    #define MM_ACC(v, base)                                                    \
        do {                                                                   \
            const int p0 = 2 * (lane + (base));                                \
            if ((v).y > 0.0f) { mn = min(mn, p0);     mx = max(mx, p0); }      \
            if ((v).w > 0.0f) { mn = min(mn, p0 + 1); mx = max(mx, p0 + 1); }  \
        } while (0)
    MM_ACC(v0,   0); MM_ACC(v1,  32); MM_ACC(v2,  64); MM_ACC(v3,  96);
    MM_ACC(v4, 128); MM_ACC(v5, 160); MM_ACC(v6, 192); MM_ACC(v7, 224);
    #undef MM_ACC

    #pragma unroll
    for (int o = 16; o; o >>= 1) {
        mn = min(mn, __shfl_down_sync(0xffffffffu, mn, o));
        mx = max(mx, __shfl_down_sync(0xffffffffu, mx, o));
    }
    if (lane == 0) {
        g_xmin[b * HH + h] = mn;
        g_xmax[b * HH + h] = mx;
    }
}

// ---------------------------------------------------------------------------
// Kernel B: grid = B fit-blocks (bids 0..B-1) + B*N*NCH size blocks.
// Fit blocks compute theta from g_xmin/g_xmax (previous-kernel data, ready
// immediately) and publish g_ready[b]. Size blocks spin briefly, then stream
// their 128-row chunk with explicit 4-deep PLAIN float4 load batches.
// ---------------------------------------------------------------------------
__global__ void __launch_bounds__(512) sizefit_kernel(const float* __restrict__ pad,
                                                      float* __restrict__ out,
                                                      int B, int N)
{
    const int tid  = threadIdx.x;
    const int lane = tid & 31;
    const int warp = tid >> 5;

    if ((int)blockIdx.x < B) {
        // ================= fit role =================
        const int b = blockIdx.x;

        const int xmin_i = g_xmin[b * HH + tid];
        const int xmax_i = g_xmax[b * HH + tid];
        const int valid  = (xmax_i >= 0 && xmin_i != xmax_i) ? 1 : 0;

        __shared__ int   wtot[16];
        __shared__ float acc[7];
        unsigned bal = __ballot_sync(0xffffffffu, valid);
        int pre = __popc(bal & ((1u << lane) - 1u));
        if (lane == 0) wtot[warp] = __popc(bal);
        if (tid < 7) acc[tid] = 0.0f;
        __syncthreads();

        int off = 0, nvalid = 0;
        #pragma unroll
        for (int i = 0; i < 16; i++) {
            int t = wtot[i];
            nvalid += t;
            if (i < warp) off += t;
        }
        const int rank = off + pre;

        int drop = (int)((float)nvalid * 0.15f);  // trunc, matches astype(int32)
        if (drop < 1) drop = 1;
        const int keep = valid && (rank >= drop) && (rank < nvalid - drop);

        const float w  = keep ? 1.0f : 0.0f;
        const float y  = (float)tid;
        const float xl = (float)xmin_i;
        const float xr = (float)xmax_i;

        float s0 = w;
        float s1 = w * y;
        float s2 = w * y * y;
        float s3 = w * xl;
        float s4 = w * y * xl;
        float s5 = w * xr;
        float s6 = w * y * xr;

        #pragma unroll
        for (int o = 16; o; o >>= 1) {
            s0 += __shfl_down_sync(0xffffffffu, s0, o);
            s1 += __shfl_down_sync(0xffffffffu, s1, o);
            s2 += __shfl_down_sync(0xffffffffu, s2, o);
            s3 += __shfl_down_sync(0xffffffffu, s3, o);
            s4 += __shfl_down_sync(0xffffffffu, s4, o);
            s5 += __shfl_down_sync(0xffffffffu, s5, o);
            s6 += __shfl_down_sync(0xffffffffu, s6, o);
        }
        if (lane == 0) {
            atomicAdd(&acc[0], s0);
            atomicAdd(&acc[1], s1);
            atomicAdd(&acc[2], s2);
            atomicAdd(&acc[3], s3);
            atomicAdd(&acc[4], s4);
            atomicAdd(&acc[5], s5);
            atomicAdd(&acc[6], s6);
        }
        __syncthreads();

        if (tid == 0) {
            const float Sw  = acc[0], Sy  = acc[1], Syy = acc[2];
            const float Sxl = acc[3], Sxyl = acc[4];
            const float Sxr = acc[5], Sxyr = acc[6];

            const float det  = Syy * Sw - Sy * Sy;
            const float safe = (det > 0.0f) ? det : 1.0f;

            float sl_l = (Sw * Sxyl - Sy * Sxl) / safe;
            float ic_l = (-Sy * Sxyl + Syy * Sxl) / safe;
            float sl_r = (Sw * Sxyr - Sy * Sxr) / safe;
            float ic_r = (-Sy * Sxyr + Syy * Sxr) / safe;
            if (!(det > 0.0f)) { sl_l = ic_l = sl_r = ic_r = 0.0f; }

            g_theta[b] = make_float4(sl_l, ic_l, sl_r, ic_r);
            __threadfence();
            atomicExch(&g_ready[b], 1);
        }
        return;
    }

    // ================= size role =================
    const int sidx = (int)blockIdx.x - B;
    const int bn   = sidx >> 2;
    const int ch   = sidx & 3;
    const int b    = bn / N;
    const int g    = tid >> 7;        // row group 0..3
    const int c    = tid & 127;       // column group: columns 4c..4c+3
    const int h0   = ch * CHROWS;     // first global row of this chunk

    __shared__ float    su [CHROWS];
    __shared__ float    su2[CHROWS];
    __shared__ float    scol[WW];
    __shared__ unsigned grpmask[4];
    __shared__ float    sred[16];

    // wait for theta (bounded: fit block runs immediately in wave 1)
    if (tid == 0) {
        while (__ldcg(&g_ready[b]) == 0) __nanosleep(64);
    }
    __syncthreads();

    if (tid < CHROWS) {
        const float4 th = __ldcg(&g_theta[b]);  // {sl_l, ic_l, sl_r, ic_r}
        const float y = (float)(h0 + tid);
        float width = (y * th.z + th.w) - (y * th.x + th.y);
        width = fmaxf(width, 1.0f);
        const float u = 3.25f / width;
        su [tid] = u;
        su2[tid] = u * u;
    }
    scol[tid] = 0.0f;
    if (tid < 4) grpmask[tid] = 0u;
    __syncthreads();

    const float4* p = (const float4*)(pad + (size_t)bn * HH * WW
                                          + (size_t)h0 * WW) + c;

    float4 colacc = make_float4(0.f, 0.f, 0.f, 0.f);
    float  inst   = 0.0f;
    unsigned lm   = 0u;

    #pragma unroll
    for (int kk = 0; kk < 32; kk += 4) {
        // issue 4 plain loads back-to-back, then consume
        const float4 w0 = p[(size_t)(g + 4 * (kk + 0)) * (WW / 4)];
        const float4 w1 = p[(size_t)(g + 4 * (kk + 1)) * (WW / 4)];
        const float4 w2 = p[(size_t)(g + 4 * (kk + 2)) * (WW / 4)];
        const float4 w3 = p[(size_t)(g + 4 * (kk + 3)) * (WW / 4)];

        #define SZ_ACC(v, k)                                                   \
            do {                                                               \
                const int hh = g + 4 * (k);                                    \
                const float u1 = su[hh], u2 = su2[hh];                         \
                colacc.x = fmaf(u1, (v).x, colacc.x);                          \
                colacc.y = fmaf(u1, (v).y, colacc.y);                          \
                colacc.z = fmaf(u1, (v).z, colacc.z);                          \
                colacc.w = fmaf(u1, (v).w, colacc.w);                          \
                inst = fmaf(u2, ((v).x + (v).y) + ((v).z + (v).w), inst);      \
                if ((v).x > 0.5f || (v).y > 0.5f ||                            \
                    (v).z > 0.5f || (v).w > 0.5f)                              \
                    lm |= (1u << (k));                                         \
            } while (0)
        SZ_ACC(w0, kk + 0);
        SZ_ACC(w1, kk + 1);
        SZ_ACC(w2, kk + 2);
        SZ_ACC(w3, kk + 3);
        #undef SZ_ACC
    }

    // row-occupied bits: OR across the 4 warps of each group
    {
        unsigned m = __reduce_or_sync(0xffffffffu, lm);
        if (lane == 0 && m) atomicOr(&grpmask[g], m);
    }

    // per-column sums: combine 4 row-groups via shared atomics
    atomicAdd(&scol[4 * c + 0], colacc.x);
    atomicAdd(&scol[4 * c + 1], colacc.y);
    atomicAdd(&scol[4 * c + 2], colacc.z);
    atomicAdd(&scol[4 * c + 3], colacc.w);

    // instance partial (block sum)
    float s = inst;
    #pragma unroll
    for (int o = 16; o; o >>= 1) s += __shfl_down_sync(0xffffffffu, s, o);
    if (lane == 0) sred[warp] = s;
    __syncthreads();

    // vertical partial: local row r handled by group r&3, iteration r>>2
    float vv = 0.0f;
    if (tid < CHROWS) {
        const unsigned bit = (grpmask[tid & 3] >> (tid >> 2)) & 1u;
        vv = bit ? su[tid] : 0.0f;
    }
    #pragma unroll
    for (int o = 16; o; o >>= 1) vv += __shfl_down_sync(0xffffffffu, vv, o);

    __shared__ float svert[4];
    if (lane == 0 && warp < 4) svert[warp] = vv;
    __syncthreads();

    if (tid == 0) {
        float ti = 0.0f;
        #pragma unroll
        for (int i = 0; i < 16; i++) ti += sred[i];
        float tv = (svert[0] + svert[1]) + (svert[2] + svert[3]);
        g_part[bn][ch][0] = ti;
        g_part[bn][ch][1] = tv;
    }

    // column partials to scratch (coalesced)
    g_colp[bn][ch][tid] = scol[tid];
    __threadfence();

    // elect last chunk-block of this slab to combine
    __shared__ int isLastC;
    __syncthreads();
    if (tid == 0) isLastC = (atomicAdd(&g_cnt[bn], 1) == NCH - 1);
    __syncthreads();

    if (isLastC) {
        __threadfence();
        float colsum = __ldcg(&g_colp[bn][0][tid]);
        colsum += __ldcg(&g_colp[bn][1][tid]);
        colsum += __ldcg(&g_colp[bn][2][tid]);
        colsum += __ldcg(&g_colp[bn][3][tid]);

        float m = colsum;
        #pragma unroll
        for (int o = 16; o; o >>= 1) m = fmaxf(m, __shfl_down_sync(0xffffffffu, m, o));
        if (lane == 0) sred[warp] = m;
        __syncthreads();

        if (tid == 0) {
            float hmax = sred[0];
            #pragma unroll
            for (int i = 1; i < 16; i++) hmax = fmaxf(hmax, sred[i]);

            float ti = 0.0f, tv = 0.0f;
            #pragma unroll
            for (int i = 0; i < NCH; i++) {
                ti += __ldcg(&g_part[bn][i][0]);
                tv += __ldcg(&g_part[bn][i][1]);
            }
            out[bn * 3 + 0] = ti;
            out[bn * 3 + 1] = hmax;
            out[bn * 3 + 2] = tv;

            g_cnt[bn] = 0;           // reset for the next graph replay
        }
    }

    // per-image completion: last size block resets the ready flag
    __syncthreads();
    if (tid == 0) {
        if (atomicAdd(&g_done[b], 1) == N * NCH - 1) {
            g_done[b] = 0;
            atomicExch(&g_ready[b], 0);
        }
    }
}

// ---------------------------------------------------------------------------
extern "C" void kernel_launch(void* const* d_in, const int* in_sizes, int n_in,
                              void* d_out, int out_size)
{
    const float* seg = (const float*)d_in[0];   // [B, H, W, 2]
    const float* pad = (const float*)d_in[1];   // [B, N, H, W]
    float* out = (float*)d_out;                 // [B, N, 3]

    const int B = in_sizes[0] / (HH * WW * 2);
    const int N = in_sizes[1] / (B * HH * WW);

    minmax_kernel<<<B * 32, 512>>>(seg);
    sizefit_kernel<<<B + B * N * NCH, 512>>>(pad, out, B, N);
}